// round 5
// baseline (speedup 1.0000x reference)
#include <cuda_runtime.h>
#include <math.h>

// ---------------- constants (problem is fixed-shape) ----------------
#define BSZ 64
#define DD  256
#define HH  1024
#define SS  2048
#define BH  (BSZ*HH)      // 65536
#define KC  32
#define HSTR 36           // encoder hs row stride (16B-aligned rows, bank-spread)
#define HSP  34           // decoder hs row stride (8B-aligned k-pair loads)
#define ENC_NB 96
#define DEC_NB 64

// ---------------- scratch (__device__ globals; no cudaMalloc allowed) ----
__device__ float g_u[(long)SS*BSZ*DD];     // 128 MB  [s*B+b][D]
__device__ float g_c[(long)SS*BSZ*HH];     // 512 MB  [s][b][H]
__device__ float g_h0[2][BH];
__device__ float g_h1a[2][BH];
__device__ float g_h1b[2][BH];
__device__ float g_h1d[2][BH];
__device__ float g_udec[BSZ*DD];
__device__ unsigned g_cnt0, g_gen0, g_cnt1, g_gen1;
__device__ volatile unsigned g_abort;

// ---------------- packed f32x2 helpers ----------------
__device__ __forceinline__ void ffma2(unsigned long long& d,
                                      unsigned long long a, unsigned long long b) {
    asm("fma.rn.f32x2 %0, %1, %2, %0;" : "+l"(d) : "l"(a), "l"(b));
}
__device__ __forceinline__ unsigned long long pack2(float lo, float hi) {
    unsigned long long r;
    asm("mov.b64 %0, {%1, %2};" : "=l"(r) : "f"(lo), "f"(hi));
    return r;
}
__device__ __forceinline__ void unpack2(unsigned long long v, float& lo, float& hi) {
    asm("mov.b64 {%0, %1}, %2;" : "=f"(lo), "=f"(hi) : "l"(v));
}
__device__ __forceinline__ void mul2(unsigned long long& d, unsigned long long a) {
    asm("mul.rn.f32x2 %0, %0, %1;" : "+l"(d) : "l"(a));
}

// ---------------- software grid barrier with hang watchdog ----------------
// If co-residency were ever violated, the spin bails after ~0.8s, sets
// g_abort, and every subsequent barrier becomes a pass-through: the kernel
// terminates (wrong results -> rel_err diagnostic) instead of hanging the
// container.
__device__ __forceinline__ void grid_sync(unsigned nb, unsigned* cnt, unsigned* gen) {
    __syncthreads();
    if (threadIdx.x == 0) {
        if (g_abort == 0u) {
            unsigned g0 = atomicAdd(gen, 0u);
            __threadfence();                       // release prior writes
            unsigned a = atomicAdd(cnt, 1u);
            if (a == nb - 1u) {
                atomicExch(cnt, 0u);
                __threadfence();
                atomicAdd(gen, 1u);
            } else {
                long iters = 0;
                while (atomicAdd(gen, 0u) == g0) {
                    __nanosleep(64);
                    if (++iters > (1L << 23)) { g_abort = 1u; __threadfence(); break; }
                    if (g_abort != 0u) break;
                }
            }
            __threadfence();                       // acquire others' writes
        }
    }
    __syncthreads();
}

// ---------------- init: zero initial states + barrier counters ----------
__global__ void init_kernel() {
    int i = blockIdx.x * blockDim.x + threadIdx.x;
    if (i < BH) { g_h0[0][i] = 0.f; g_h1a[0][i] = 0.f; g_h1b[0][i] = 0.f; }
    if (i == 0) { g_cnt0 = 0u; g_gen0 = 0u; g_cnt1 = 0u; g_gen1 = 0u; g_abort = 0u; }
}

// ========================================================================
// FRONT: input stack over all S*B rows + c = u @ Wx0 + b0
// ========================================================================
__global__ __launch_bounds__(256)
void stack_kernel(const float* __restrict__ src,
                  const float* __restrict__ sW, const float* __restrict__ sb,
                  const float* __restrict__ lg, const float* __restrict__ lb,
                  float* __restrict__ dst, int S_)
{
    __shared__ float xs[16][DD];
    __shared__ float redS[16][64];
    __shared__ float redQ[16][64];
    __shared__ float mus[16], rsd[16];
    const int tid = threadIdx.x;
    const int r0 = blockIdx.x * 16;

    for (int i = tid; i < 16*DD; i += 256) {
        int row = i >> 8, col = i & 255;
        int rr = r0 + row;
        int s = rr >> 6, b = rr & 63;                 // row = s*B + b
        xs[row][col] = src[((long)b*S_ + s)*DD + col];
    }
    __syncthreads();

    const int c0 = (tid & 63) * 4;
    const int r4 = (tid >> 6) * 4;
    float y[4][4];
    #pragma unroll
    for (int a = 0; a < 4; a++)
        #pragma unroll
        for (int b2 = 0; b2 < 4; b2++) y[a][b2] = 0.f;

    for (int k = 0; k < DD; k++) {
        float4 wv = *(const float4*)&sW[k*DD + c0];
        #pragma unroll
        for (int rr2 = 0; rr2 < 4; rr2++) {
            float hv = xs[r4+rr2][k];
            y[rr2][0] += hv*wv.x; y[rr2][1] += hv*wv.y;
            y[rr2][2] += hv*wv.z; y[rr2][3] += hv*wv.w;
        }
    }
    float4 bv = *(const float4*)&sb[c0];
    #pragma unroll
    for (int rr2 = 0; rr2 < 4; rr2++) {
        y[rr2][0] += bv.x; y[rr2][1] += bv.y; y[rr2][2] += bv.z; y[rr2][3] += bv.w;
        #pragma unroll
        for (int cc = 0; cc < 4; cc++) {
            float v = y[rr2][cc];
            y[rr2][cc] = 0.5f * v * (1.f + erff(v * 0.70710678118654752f));
        }
    }
    #pragma unroll
    for (int rr2 = 0; rr2 < 4; rr2++) {
        float s = 0.f, q = 0.f;
        #pragma unroll
        for (int cc = 0; cc < 4; cc++) { s += y[rr2][cc]; q += y[rr2][cc]*y[rr2][cc]; }
        redS[r4+rr2][tid & 63] = s;
        redQ[r4+rr2][tid & 63] = q;
    }
    __syncthreads();
    int wid = tid >> 5, lane = tid & 31;
    for (int row = wid*2; row < wid*2+2; row++) {
        float s = redS[row][lane] + redS[row][lane+32];
        float q = redQ[row][lane] + redQ[row][lane+32];
        #pragma unroll
        for (int off = 16; off; off >>= 1) {
            s += __shfl_down_sync(0xffffffffu, s, off);
            q += __shfl_down_sync(0xffffffffu, q, off);
        }
        if (lane == 0) {
            float mu = s * (1.f/256.f);
            float var = q * (1.f/256.f) - mu*mu;
            mus[row] = mu; rsd[row] = rsqrtf(var + 1e-5f);
        }
    }
    __syncthreads();
    float4 gv = *(const float4*)&lg[c0];
    float4 lbv = *(const float4*)&lb[c0];
    #pragma unroll
    for (int rr2 = 0; rr2 < 4; rr2++) {
        int row = r4 + rr2;
        float mu = mus[row], rs = rsd[row];
        float4 o;
        o.x = gv.x*(y[rr2][0]-mu)*rs + lbv.x;
        o.y = gv.y*(y[rr2][1]-mu)*rs + lbv.y;
        o.z = gv.z*(y[rr2][2]-mu)*rs + lbv.z;
        o.w = gv.w*(y[rr2][3]-mu)*rs + lbv.w;
        *(float4*)&dst[(long)(r0+row)*DD + c0] = o;
    }
}

__global__ __launch_bounds__(256)
void cgemm_kernel(const float* __restrict__ u, const float* __restrict__ Wx0,
                  const float* __restrict__ b0, float* __restrict__ cbuf)
{
    __shared__ float us[16][DD];
    const int tid = threadIdx.x;
    const int r0 = blockIdx.x * 16;
    const int colbase = blockIdx.y * 256;
    for (int i = tid; i < 16*DD; i += 256) {
        int row = i >> 8, col = i & 255;
        us[row][col] = u[(long)(r0+row)*DD + col];
    }
    __syncthreads();
    const int c0 = (tid & 63) * 4 + colbase;
    const int r4 = (tid >> 6) * 4;
    unsigned long long acc2[4][2];
    #pragma unroll
    for (int a = 0; a < 4; a++) { acc2[a][0] = 0ull; acc2[a][1] = 0ull; }
    for (int k = 0; k < DD; k++) {
        float4 wv = *(const float4*)&Wx0[(long)k*HH + c0];
        unsigned long long w01 = pack2(wv.x, wv.y);
        unsigned long long w23 = pack2(wv.z, wv.w);
        #pragma unroll
        for (int rr2 = 0; rr2 < 4; rr2++) {
            float hv = us[r4+rr2][k];
            unsigned long long hp = pack2(hv, hv);
            ffma2(acc2[rr2][0], hp, w01);
            ffma2(acc2[rr2][1], hp, w23);
        }
    }
    float4 bv = *(const float4*)&b0[c0];
    #pragma unroll
    for (int rr2 = 0; rr2 < 4; rr2++) {
        float a0,a1,a2,a3;
        unpack2(acc2[rr2][0], a0, a1);
        unpack2(acc2[rr2][1], a2, a3);
        float4 o;
        o.x = a0+bv.x; o.y = a1+bv.y; o.z = a2+bv.z; o.w = a3+bv.w;
        *(float4*)&cbuf[(long)(r0+r4+rr2)*HH + c0] = o;
    }
}

// ========================================================================
// ENCODER: persistent kernel, 96 blocks, weights resident in smem.
// Phase t: g0 computes h0_t ; g1+g2 compute h1_{t-1} (split sum).
// ========================================================================
__global__ __launch_bounds__(256, 1)
void enc_kernel(const float* __restrict__ cbuf,
                const float* __restrict__ Wh0, const float* __restrict__ Wh1,
                const float* __restrict__ Wx1, const float* __restrict__ b1,
                const float* __restrict__ pd0, const float* __restrict__ pd1,
                int S)
{
    extern __shared__ float es[];
    float* Wsl = es;                       // k-pair-packed weight slice: 32768 floats
    float* hsb = es + HH*32;               // 2 x [64][HSTR] h staging

    const int tid = threadIdx.x;
    const int g  = blockIdx.x >> 5;
    const int cb = (blockIdx.x & 31) * 32;
    const float* W = (g == 0) ? Wh0 : (g == 1) ? Wh1 : Wx1;

    // load + pack weight slice once: Wsl[kp*64 + c*2 + parity]
    for (int i = tid; i < HH*32; i += 256) {
        int k = i >> 5, cc = i & 31;
        Wsl[(((k >> 1) * 32 + cc) << 1) + (k & 1)] = __ldg(&W[(long)k*HH + cb + cc]);
    }
    const float d0v = __ldg(pd0);
    const float d1v = __ldg(pd1);
    __syncthreads();

    const int c8 = tid & 7;                // col lane: cols cb + c8 + 8j
    const int r0 = (tid >> 3) * 2;         // row pair
    const int sr = tid >> 2;               // staging row 0..63
    const int sc = (tid & 3) * 8;          // staging col group

    for (int t = 1; t <= S + 1; t++) {
        const int active = (g == 0) ? (t <= S) : (t >= 2);
        const float* h0r  = g_h0[(t-1) & 1];
        float*       h0w  = g_h0[t & 1];
        const float* h1ra = g_h1a[t & 1];
        const float* h1rb = g_h1b[t & 1];
        float*       h1wa = g_h1a[(t-1) & 1];
        float*       h1wb = g_h1b[(t-1) & 1];

        if (active) {
            const float* Ha = (g == 1) ? h1ra : h0r;
            const float* Hb = (g == 1) ? h1rb : nullptr;
            unsigned long long accp[2][4];
            #pragma unroll
            for (int rr = 0; rr < 2; rr++)
                #pragma unroll
                for (int j = 0; j < 4; j++) accp[rr][j] = 0ull;

            const float* hp = Ha + (long)sr * HH + sc;
            const float* hq = Hb ? (Hb + (long)sr * HH + sc) : nullptr;
            float4 pa = __ldcg((const float4*)hp);
            float4 pb = __ldcg((const float4*)(hp + 4));
            if (hq) {
                float4 qa = __ldcg((const float4*)hq);
                float4 qb = __ldcg((const float4*)(hq + 4));
                pa.x += qa.x; pa.y += qa.y; pa.z += qa.z; pa.w += qa.w;
                pb.x += qb.x; pb.y += qb.y; pb.z += qb.z; pb.w += qb.w;
            }
            #pragma unroll 2
            for (int ch = 0; ch < 32; ch++) {
                float* hb2 = hsb + (ch & 1) * (64 * HSTR);
                *(float4*)&hb2[sr * HSTR + sc]     = pa;
                *(float4*)&hb2[sr * HSTR + sc + 4] = pb;
                __syncthreads();
                if (ch < 31) {
                    int ko = (ch + 1) * KC;
                    pa = __ldcg((const float4*)(hp + ko));
                    pb = __ldcg((const float4*)(hp + ko + 4));
                    if (hq) {
                        float4 qa = __ldcg((const float4*)(hq + ko));
                        float4 qb = __ldcg((const float4*)(hq + ko + 4));
                        pa.x += qa.x; pa.y += qa.y; pa.z += qa.z; pa.w += qa.w;
                        pb.x += qb.x; pb.y += qb.y; pb.z += qb.z; pb.w += qb.w;
                    }
                }
                const float* wbase = Wsl + (ch * 16) * 64;
                #pragma unroll
                for (int kp = 0; kp < 16; kp++) {
                    unsigned long long hp0 =
                        *(const unsigned long long*)&hb2[r0 * HSTR + 2*kp];
                    unsigned long long hp1 =
                        *(const unsigned long long*)&hb2[(r0+1) * HSTR + 2*kp];
                    const float* wr = wbase + kp * 64;
                    #pragma unroll
                    for (int j = 0; j < 4; j++) {
                        unsigned long long wv =
                            *(const unsigned long long*)&wr[(c8 + 8*j) * 2];
                        ffma2(accp[0][j], hp0, wv);
                        ffma2(accp[1][j], hp1, wv);
                    }
                }
            }
            // finalize + write
            if (g == 0) {
                const float* cv = cbuf + (long)(t-1) * BH;
                #pragma unroll
                for (int rr = 0; rr < 2; rr++)
                    #pragma unroll
                    for (int j = 0; j < 4; j++) {
                        int c = cb + c8 + 8*j;
                        float lo, hi; unpack2(accp[rr][j], lo, hi);
                        float v = d0v * (lo + hi) + __ldcg(&cv[(r0+rr)*HH + c]);
                        __stcg(&h0w[(r0+rr)*HH + c], v);
                    }
            } else if (g == 1) {
                #pragma unroll
                for (int rr = 0; rr < 2; rr++)
                    #pragma unroll
                    for (int j = 0; j < 4; j++) {
                        int c = cb + c8 + 8*j;
                        float lo, hi; unpack2(accp[rr][j], lo, hi);
                        float v = d1v * (lo + hi) + __ldg(&b1[c]);
                        __stcg(&h1wa[(r0+rr)*HH + c], v);
                    }
            } else {
                #pragma unroll
                for (int rr = 0; rr < 2; rr++)
                    #pragma unroll
                    for (int j = 0; j < 4; j++) {
                        int c = cb + c8 + 8*j;
                        float lo, hi; unpack2(accp[rr][j], lo, hi);
                        __stcg(&h1wb[(r0+rr)*HH + c], lo + hi);
                    }
            }
        }
        grid_sync(ENC_NB, &g_cnt0, &g_gen0);
    }
}

// ========================================================================
// DECODER: persistent kernel, 64 blocks, 4 staged sub-steps + grid syncs
// ========================================================================
template<int CW>
__device__ __forceinline__ void mm2(
    unsigned long long accp[2][CW],
    const float* __restrict__ Ha, const float* __restrict__ Hb, long ldh,
    const float* __restrict__ W, int ldw, int K, int colbase,
    float* hs, float* ws, int tid)
{
    const int TC = 8*CW;
    const int NH = (64*KC)/256;     // 8
    const int NW = (KC/2*TC)/256;   // 1 for CW=2
    float  hreg[NH];
    float2 wreg[NW];

    const int c0 = (tid & 7) * CW;
    const int r0 = (tid >> 3) * 2;

    #pragma unroll
    for (int j = 0; j < NH; j++) {
        int i = tid + 256*j; int r = i >> 5, kk = i & 31;
        float v = __ldcg(&Ha[(long)r*ldh + kk]);
        if (Hb) v += __ldcg(&Hb[(long)r*ldh + kk]);
        hreg[j] = v;
    }
    #pragma unroll
    for (int j = 0; j < NW; j++) {
        int i = tid + 256*j; int kp = i / TC, c = i - kp*TC;
        wreg[j].x = __ldg(&W[(long)(2*kp)  *ldw + colbase + c]);
        wreg[j].y = __ldg(&W[(long)(2*kp+1)*ldw + colbase + c]);
    }

    for (int k0 = 0; k0 < K; k0 += KC) {
        __syncthreads();
        #pragma unroll
        for (int j = 0; j < NH; j++) {
            int i = tid + 256*j; int r = i >> 5, kk = i & 31;
            hs[r*HSP + kk] = hreg[j];
        }
        #pragma unroll
        for (int j = 0; j < NW; j++) {
            int i = tid + 256*j; int kp = i / TC, c = i - kp*TC;
            *(float2*)&ws[(kp*TC + c)*2] = wreg[j];
        }
        __syncthreads();

        int kn = k0 + KC;
        if (kn < K) {
            #pragma unroll
            for (int j = 0; j < NH; j++) {
                int i = tid + 256*j; int r = i >> 5, kk = i & 31;
                float v = __ldcg(&Ha[(long)r*ldh + kn + kk]);
                if (Hb) v += __ldcg(&Hb[(long)r*ldh + kn + kk]);
                hreg[j] = v;
            }
            #pragma unroll
            for (int j = 0; j < NW; j++) {
                int i = tid + 256*j; int kp = i / TC, c = i - kp*TC;
                wreg[j].x = __ldg(&W[(long)(kn+2*kp)  *ldw + colbase + c]);
                wreg[j].y = __ldg(&W[(long)(kn+2*kp+1)*ldw + colbase + c]);
            }
        }

        #pragma unroll
        for (int kp = 0; kp < KC/2; kp++) {
            unsigned long long hp0 = *(const unsigned long long*)&hs[ r0   *HSP + 2*kp];
            unsigned long long hp1 = *(const unsigned long long*)&hs[(r0+1)*HSP + 2*kp];
            #pragma unroll
            for (int cc = 0; cc < CW; cc++) {
                unsigned long long wv =
                    *(const unsigned long long*)&ws[(kp*TC + c0 + cc)*2];
                ffma2(accp[0][cc], hp0, wv);
                ffma2(accp[1][cc], hp1, wv);
            }
        }
    }
}

__device__ void stack_stage(const float* src, long rowStride, int rbase,
                            const float* sW, const float* sb,
                            const float* lg, const float* lb,
                            float* dst, float* sm, int tid)
{
    float* xs   = sm;            // 16*256
    float* redS = sm + 4096;     // 16*64
    float* redQ = sm + 5120;     // 16*64
    float* mus  = sm + 6144;
    float* rsd  = sm + 6160;

    for (int i = tid; i < 16*DD; i += 256) {
        int row = i >> 8, col = i & 255;
        xs[row*DD + col] = __ldcg(&src[(long)(rbase+row)*rowStride + col]);
    }
    __syncthreads();

    const int c0 = (tid & 63) * 4;
    const int r4 = (tid >> 6) * 4;
    float y[4][4];
    #pragma unroll
    for (int a = 0; a < 4; a++)
        #pragma unroll
        for (int b2 = 0; b2 < 4; b2++) y[a][b2] = 0.f;

    for (int k = 0; k < DD; k++) {
        float4 wv = *(const float4*)&sW[k*DD + c0];
        #pragma unroll
        for (int rr2 = 0; rr2 < 4; rr2++) {
            float hv = xs[(r4+rr2)*DD + k];
            y[rr2][0] += hv*wv.x; y[rr2][1] += hv*wv.y;
            y[rr2][2] += hv*wv.z; y[rr2][3] += hv*wv.w;
        }
    }
    float4 bv = *(const float4*)&sb[c0];
    #pragma unroll
    for (int rr2 = 0; rr2 < 4; rr2++) {
        y[rr2][0] += bv.x; y[rr2][1] += bv.y; y[rr2][2] += bv.z; y[rr2][3] += bv.w;
        #pragma unroll
        for (int cc = 0; cc < 4; cc++) {
            float v = y[rr2][cc];
            y[rr2][cc] = 0.5f * v * (1.f + erff(v * 0.70710678118654752f));
        }
    }
    #pragma unroll
    for (int rr2 = 0; rr2 < 4; rr2++) {
        float s = 0.f, q = 0.f;
        #pragma unroll
        for (int cc = 0; cc < 4; cc++) { s += y[rr2][cc]; q += y[rr2][cc]*y[rr2][cc]; }
        redS[(r4+rr2)*64 + (tid & 63)] = s;
        redQ[(r4+rr2)*64 + (tid & 63)] = q;
    }
    __syncthreads();
    int wid = tid >> 5, lane = tid & 31;
    for (int row = wid*2; row < wid*2+2; row++) {
        float s = redS[row*64 + lane] + redS[row*64 + lane+32];
        float q = redQ[row*64 + lane] + redQ[row*64 + lane+32];
        #pragma unroll
        for (int off = 16; off; off >>= 1) {
            s += __shfl_down_sync(0xffffffffu, s, off);
            q += __shfl_down_sync(0xffffffffu, q, off);
        }
        if (lane == 0) {
            float mu = s * (1.f/256.f);
            float var = q * (1.f/256.f) - mu*mu;
            mus[row] = mu; rsd[row] = rsqrtf(var + 1e-5f);
        }
    }
    __syncthreads();
    float4 gv = *(const float4*)&lg[c0];
    float4 lbv = *(const float4*)&lb[c0];
    #pragma unroll
    for (int rr2 = 0; rr2 < 4; rr2++) {
        int row = r4 + rr2;
        float mu = mus[row], rs = rsd[row];
        __stcg(&dst[(long)(rbase+row)*DD + c0  ], gv.x*(y[rr2][0]-mu)*rs + lbv.x);
        __stcg(&dst[(long)(rbase+row)*DD + c0+1], gv.y*(y[rr2][1]-mu)*rs + lbv.y);
        __stcg(&dst[(long)(rbase+row)*DD + c0+2], gv.z*(y[rr2][2]-mu)*rs + lbv.z);
        __stcg(&dst[(long)(rbase+row)*DD + c0+3], gv.w*(y[rr2][3]-mu)*rs + lbv.w);
    }
}

__device__ void dec_h0_stage(const float* h0r, float* h0w, const float* Wh0,
                             const float* udec, const float* Wx0,
                             const float* b0, const float* pd0,
                             int colbase, float* hs, float* ws, int tid)
{
    unsigned long long accp[2][2] = {{0ull,0ull},{0ull,0ull}};
    mm2<2>(accp, h0r, nullptr, HH, Wh0, HH, HH, colbase, hs, ws, tid);
    float d0v = __ldg(pd0);
    unsigned long long dp = pack2(d0v, d0v);
    mul2(accp[0][0], dp); mul2(accp[0][1], dp);
    mul2(accp[1][0], dp); mul2(accp[1][1], dp);
    mm2<2>(accp, udec, nullptr, DD, Wx0, HH, DD, colbase, hs, ws, tid);
    const int c0 = (tid & 7) * 2;
    const int r0 = (tid >> 3) * 2;
    #pragma unroll
    for (int rr = 0; rr < 2; rr++)
        #pragma unroll
        for (int cc = 0; cc < 2; cc++) {
            int c = colbase + c0 + cc;
            float lo, hi; unpack2(accp[rr][cc], lo, hi);
            __stcg(&h0w[(r0+rr)*HH + c], lo + hi + __ldg(&b0[c]));
        }
}

__device__ void dec_h1_stage(const float* h1ra, const float* h1rb, float* h1w,
                             const float* Wh1, const float* h0n,
                             const float* Wx1, const float* b1, const float* pd1,
                             int colbase, float* hs, float* ws, int tid)
{
    unsigned long long accp[2][2] = {{0ull,0ull},{0ull,0ull}};
    mm2<2>(accp, h1ra, h1rb, HH, Wh1, HH, HH, colbase, hs, ws, tid);
    float d1v = __ldg(pd1);
    unsigned long long dp = pack2(d1v, d1v);
    mul2(accp[0][0], dp); mul2(accp[0][1], dp);
    mul2(accp[1][0], dp); mul2(accp[1][1], dp);
    mm2<2>(accp, h0n, nullptr, HH, Wx1, HH, HH, colbase, hs, ws, tid);
    const int c0 = (tid & 7) * 2;
    const int r0 = (tid >> 3) * 2;
    #pragma unroll
    for (int rr = 0; rr < 2; rr++)
        #pragma unroll
        for (int cc = 0; cc < 2; cc++) {
            int c = colbase + c0 + cc;
            float lo, hi; unpack2(accp[rr][cc], lo, hi);
            __stcg(&h1w[(r0+rr)*HH + c], lo + hi + __ldg(&b1[c]));
        }
}

__device__ void outproj_stage(const float* h1a, const float* h1b,
                              const float* projW, const float* projb,
                              const float* cur, long curld,
                              const float* inW, const float* inb,
                              const float* pskw,
                              float* outp, long outld,
                              int colbase, float* hs, float* ws, int tid)
{
    unsigned long long a1[2][2] = {{0ull,0ull},{0ull,0ull}};
    unsigned long long a2[2][2] = {{0ull,0ull},{0ull,0ull}};
    mm2<2>(a1, h1a, h1b, HH, projW, DD, HH, colbase, hs, ws, tid);
    mm2<2>(a2, cur, nullptr, curld, inW, DD, DD, colbase, hs, ws, tid);
    float sk = __ldg(pskw);
    const int c0 = (tid & 7) * 2;
    const int r0 = (tid >> 3) * 2;
    #pragma unroll
    for (int rr = 0; rr < 2; rr++)
        #pragma unroll
        for (int cc = 0; cc < 2; cc++) {
            int c = colbase + c0 + cc;
            float l1, h1v, l2, h2v;
            unpack2(a1[rr][cc], l1, h1v);
            unpack2(a2[rr][cc], l2, h2v);
            float v = (l1 + h1v) + __ldg(&projb[c])
                    + sk * ((l2 + h2v) + __ldg(&inb[c]));
            __stcg(&outp[(long)(r0+rr)*outld + c], v);
        }
}

__global__ __launch_bounds__(256, 1)
void dec_kernel(const float* __restrict__ x,
                const float* __restrict__ sW, const float* __restrict__ sb,
                const float* __restrict__ lg, const float* __restrict__ lb,
                const float* __restrict__ Wx0, const float* __restrict__ b0,
                const float* __restrict__ Wh0, const float* __restrict__ pd0,
                const float* __restrict__ Wx1, const float* __restrict__ b1,
                const float* __restrict__ Wh1, const float* __restrict__ pd1,
                const float* __restrict__ inW, const float* __restrict__ inb,
                const float* __restrict__ pskw,
                const float* __restrict__ projW, const float* __restrict__ projb,
                float* __restrict__ out, int S, int F)
{
    __shared__ float smbuf[8192];
    const int b = blockIdx.x, tid = threadIdx.x;
    float* hs = smbuf;
    float* ws = smbuf + 64*HSP;

    // initial prediction: out[:,0,:] = out_proj(h1_enc, x[:,S-1,:])
    if (b < 16)
        outproj_stage(g_h1a[0], g_h1b[0], projW, projb,
                      x + (long)(S-1)*DD, (long)S*DD, inW, inb, pskw,
                      out, (long)F*DD, b*16, hs, ws, tid);
    grid_sync(DEC_NB, &g_cnt1, &g_gen1);

    for (int j = 1; j < F; j++) {
        if (b < 4)
            stack_stage(out + (long)(j-1)*DD, (long)F*DD, b*16,
                        sW, sb, lg, lb, g_udec, smbuf, tid);
        grid_sync(DEC_NB, &g_cnt1, &g_gen1);

        const float* h0r = g_h0[(j-1) & 1];
        float*       h0w = g_h0[j & 1];
        dec_h0_stage(h0r, h0w, Wh0, g_udec, Wx0, b0, pd0, b*16, hs, ws, tid);
        grid_sync(DEC_NB, &g_cnt1, &g_gen1);

        const float* h1ra = (j == 1) ? g_h1a[0] : g_h1d[(j-1) & 1];
        const float* h1rb = (j == 1) ? g_h1b[0] : nullptr;
        float*       h1w  = g_h1d[j & 1];
        dec_h1_stage(h1ra, h1rb, h1w, Wh1, h0w, Wx1, b1, pd1, b*16, hs, ws, tid);
        grid_sync(DEC_NB, &g_cnt1, &g_gen1);

        if (b < 16)
            outproj_stage(h1w, nullptr, projW, projb,
                          out + (long)(j-1)*DD, (long)F*DD, inW, inb, pskw,
                          out + (long)j*DD, (long)F*DD, b*16, hs, ws, tid);
        grid_sync(DEC_NB, &g_cnt1, &g_gen1);
    }
}

// ---------------- host driver ----------------
extern "C" void kernel_launch(void* const* d_in, const int* in_sizes, int n_in,
                              void* d_out, int out_size)
{
    const float* x       = (const float*)d_in[0];
    const float* stack_W = (const float*)d_in[1];
    const float* stack_b = (const float*)d_in[2];
    const float* ln_g    = (const float*)d_in[3];
    const float* ln_b    = (const float*)d_in[4];
    const float* Wx0     = (const float*)d_in[5];
    const float* b0      = (const float*)d_in[6];
    const float* Wh0     = (const float*)d_in[7];
    const float* d0      = (const float*)d_in[8];
    const float* Wx1     = (const float*)d_in[9];
    const float* b1      = (const float*)d_in[10];
    const float* Wh1     = (const float*)d_in[11];
    const float* d1      = (const float*)d_in[12];
    const float* inW     = (const float*)d_in[13];
    const float* inb     = (const float*)d_in[14];
    const float* skw     = (const float*)d_in[15];
    const float* projW   = (const float*)d_in[16];
    const float* projb   = (const float*)d_in[17];

    const int S = in_sizes[0] / (BSZ*DD);   // 2048
    const int F = out_size / (BSZ*DD);      // 128
    float* out = (float*)d_out;

    float *pu, *pc;
    cudaGetSymbolAddress((void**)&pu, g_u);
    cudaGetSymbolAddress((void**)&pc, g_c);

    const int enc_smem = (HH*32 + 2*64*HSTR) * (int)sizeof(float);  // 149504
    cudaFuncSetAttribute(enc_kernel, cudaFuncAttributeMaxDynamicSharedMemorySize,
                         enc_smem);

    init_kernel<<<(BH + 255)/256, 256>>>();

    stack_kernel<<<(S*BSZ)/16, 256>>>(x, stack_W, stack_b, ln_g, ln_b, pu, S);

    dim3 gc((S*BSZ)/16, HH/256);
    cgemm_kernel<<<gc, 256>>>(pu, Wx0, b0, pc);

    enc_kernel<<<ENC_NB, 256, enc_smem>>>(pc, Wh0, Wh1, Wx1, b1, d0, d1, S);

    dec_kernel<<<DEC_NB, 256>>>(x, stack_W, stack_b, ln_g, ln_b,
                                Wx0, b0, Wh0, d0, Wx1, b1, Wh1, d1,
                                inW, inb, skw, projW, projb, out, S, F);
}